// round 1
// baseline (speedup 1.0000x reference)
#include <cuda_runtime.h>
#include <math.h>

// Problem: out = LayerNorm(Re(FFT(x, axis=-1))), x: (4,4096,2048) fp32.
// Re(FFT)[k] = sum_c x[c] cos(2*pi*k*c/C)  -> GEMM vs fixed cosine matrix.
// Symmetries used:
//   y[C-k] = y[k]                 -> only k=0..1024 computed, mirrored on store
//   cos(.,c) == cos(.,C-c)        -> fold s[c]=x[c]+x[C-c], K=1025
//   mean(y) = x[0]
//   E[y^2]  = 0.5*(sum x^2 + sum x[c]*x[(C-c)%C])   (Parseval identities)

#define ROWS   16384      // B*N
#define CDIM   2048
#define KD     1025       // folded K (c = 0..1024)
#define KP     1032       // padded K (multiple of 8, zero-filled)
#define NOUT   1025       // unique outputs k = 0..1024
#define NP     1152       // padded N (9 tiles of 128, zero-filled)

#define BM 128
#define BN 128
#define BK 8

__device__ float g_S[ROWS * KP];     // folded inputs, zero-padded K
__device__ float g_T[KP * NP];       // cosine matrix, zero-padded
__device__ float g_mu[ROWS];
__device__ float g_rs[ROWS];

// ---------------------------------------------------------------------------
// Cosine table: T[c][k] = cos(2*pi*k*c/2048) = cospi(k*c/1024), zeros in pads.
// k*c <= 1024*1024 = 2^20 < 2^24: exactly representable in fp32; /1024 exact.
// ---------------------------------------------------------------------------
__global__ void init_table_kernel() {
    int idx = blockIdx.x * blockDim.x + threadIdx.x;
    if (idx >= KP * NP) return;
    int c = idx / NP;
    int k = idx - c * NP;
    float v = 0.0f;
    if (c < KD && k < NOUT) {
        v = cospif((float)(k * c) * (1.0f / 1024.0f));
    }
    g_T[idx] = v;
}

// ---------------------------------------------------------------------------
// Per-row prep: fold x into s[0..1024], compute mu and rstd analytically.
// One block of 256 threads per row.
// ---------------------------------------------------------------------------
__global__ __launch_bounds__(256) void prep_kernel(const float* __restrict__ x) {
    __shared__ float sx[CDIM];
    __shared__ float w1[8], w2[8];
    int row = blockIdx.x;
    int tid = threadIdx.x;
    const float* xr = x + (size_t)row * CDIM;

    float sumsq = 0.0f;
    #pragma unroll
    for (int i = tid; i < CDIM; i += 256) {
        float v = xr[i];
        sx[i] = v;
        sumsq += v * v;
    }
    __syncthreads();

    float sumrev = 0.0f;
    #pragma unroll
    for (int i = tid; i < CDIM; i += 256) {
        sumrev += sx[i] * sx[(CDIM - i) & (CDIM - 1)];
    }

    // fold into g_S
    float* Sr = g_S + (size_t)row * KP;
    for (int c = tid; c < KP; c += 256) {
        float v;
        if (c == 0)          v = sx[0];
        else if (c == 1024)  v = sx[1024];
        else if (c < 1024)   v = sx[c] + sx[CDIM - c];
        else                 v = 0.0f;     // pad 1025..1031
        Sr[c] = v;
    }

    // block reduce
    #pragma unroll
    for (int o = 16; o > 0; o >>= 1) {
        sumsq  += __shfl_xor_sync(0xffffffffu, sumsq, o);
        sumrev += __shfl_xor_sync(0xffffffffu, sumrev, o);
    }
    if ((tid & 31) == 0) { w1[tid >> 5] = sumsq; w2[tid >> 5] = sumrev; }
    __syncthreads();
    if (tid == 0) {
        float a = 0.0f, b = 0.0f;
        #pragma unroll
        for (int i = 0; i < 8; i++) { a += w1[i]; b += w2[i]; }
        float mu  = sx[0];
        float ey2 = 0.5f * (a + b) * (1.0f / (float)CDIM) * (float)CDIM; // = 0.5*(a+b) ... keep explicit
        ey2 = 0.5f * (a + b) / (float)CDIM * (float)CDIM;                // no-op clarity
        ey2 = 0.5f * ((a + b) / (float)CDIM) * (float)CDIM;              // final value below
        ey2 = 0.5f * (a + b) / (float)CDIM;                              // E over k needs /C:
        // Sum_k y^2 = (C/2)*(a+b)  =>  E[y^2] = (a+b)/2  ... careful:
        // (1/C) * (C/2)*(a+b) = (a+b)/2
        ey2 = 0.5f * (a + b);
        float var = ey2 - mu * mu;
        g_mu[row] = mu;
        g_rs[row] = rsqrtf(var + 1e-5f);
    }
}

// ---------------------------------------------------------------------------
// SGEMM Z = S @ T with fused LayerNorm epilogue + mirrored store.
// 128x128 tile, 256 threads, 8x8 per thread, BK=8.
// ---------------------------------------------------------------------------
__global__ __launch_bounds__(256) void gemm_ln_kernel(const float* __restrict__ gamma,
                                                      const float* __restrict__ beta,
                                                      float* __restrict__ out) {
    __shared__ float As[BK][BM];
    __shared__ float Bs[BK][BN];

    int m0 = blockIdx.y * BM;
    int n0 = blockIdx.x * BN;
    int tid = threadIdx.x;

    // A tile load: 128 rows x 8 cols = 1024 floats, float4 each thread
    int ar = tid >> 1;          // 0..127
    int ac = (tid & 1) * 4;     // 0 or 4
    // B tile load: 8 rows x 128 cols
    int br = tid >> 5;          // 0..7
    int bc = (tid & 31) * 4;    // 0..124

    const float* Aptr = g_S + (size_t)(m0 + ar) * KP + ac;
    const float* Bptr = g_T + (size_t)br * NP + (n0 + bc);

    float acc[8][8];
    #pragma unroll
    for (int i = 0; i < 8; i++)
        #pragma unroll
        for (int j = 0; j < 8; j++) acc[i][j] = 0.0f;

    int tx = tid & 15;   // 0..15 -> n
    int ty = tid >> 4;   // 0..15 -> m

    for (int k0 = 0; k0 < KP; k0 += BK) {
        float4 av = *(const float4*)(Aptr + k0);
        float4 bv = *(const float4*)(Bptr + (size_t)k0 * NP);
        As[ac + 0][ar] = av.x;
        As[ac + 1][ar] = av.y;
        As[ac + 2][ar] = av.z;
        As[ac + 3][ar] = av.w;
        *(float4*)&Bs[br][bc] = bv;
        __syncthreads();

        #pragma unroll
        for (int k = 0; k < BK; k++) {
            float ra[8], rb[8];
            #pragma unroll
            for (int i = 0; i < 4; i++) {
                ((float4*)ra)[0] = *(const float4*)&As[k][ty * 8];
                ((float4*)ra)[1] = *(const float4*)&As[k][ty * 8 + 4];
                ((float4*)rb)[0] = *(const float4*)&Bs[k][tx * 8];
                ((float4*)rb)[1] = *(const float4*)&Bs[k][tx * 8 + 4];
                break;
            }
            #pragma unroll
            for (int i = 0; i < 8; i++)
                #pragma unroll
                for (int j = 0; j < 8; j++)
                    acc[i][j] = fmaf(ra[i], rb[j], acc[i][j]);
        }
        __syncthreads();
    }

    // Epilogue: normalize, apply gamma/beta, mirrored store y[2048-k]=y[k]
    #pragma unroll
    for (int i = 0; i < 8; i++) {
        int m = m0 + ty * 8 + i;
        float mu = g_mu[m];
        float rs = g_rs[m];
        float* orow = out + (size_t)m * CDIM;
        #pragma unroll
        for (int j = 0; j < 8; j++) {
            int n = n0 + tx * 8 + j;
            if (n < NOUT) {
                float z = (acc[i][j] - mu) * rs;
                orow[n] = z * gamma[n] + beta[n];
                if (n >= 1 && n < 1024) {
                    int nm = CDIM - n;
                    orow[nm] = z * gamma[nm] + beta[nm];
                }
            }
        }
    }
}

extern "C" void kernel_launch(void* const* d_in, const int* in_sizes, int n_in,
                              void* d_out, int out_size) {
    const float* x     = (const float*)d_in[0];
    const float* gamma = (const float*)d_in[1];
    const float* beta  = (const float*)d_in[2];
    float* out = (float*)d_out;

    init_table_kernel<<<(KP * NP + 255) / 256, 256>>>();
    prep_kernel<<<ROWS, 256>>>(x);
    dim3 grid((NP) / BN, ROWS / BM);   // 9 x 128
    gemm_ln_kernel<<<grid, 256>>>(gamma, beta, out);
}

// round 3
// speedup vs baseline: 5.4142x; 5.4142x over previous
#include <cuda_runtime.h>
#include <cuda_fp16.h>
#include <math.h>
#include <stdint.h>

// out = LayerNorm(Re(FFT(x, axis=-1))), x: (4,4096,2048) fp32.
// Re(FFT)[k] = sum_c x[c] cos(2*pi*k*c/2048).
// Identities (verified in R1, rel_err 5.9e-7 fp32):
//   y[2048-k] = y[k]                        -> compute k=0..1023, mirror store
//   s[c] = x[c]+x[2048-c] (c=1..1023), s[1024]=x[1024]
//   mean_k(y) = x[0]  -> dropping c=0 from the GEMM yields y-mu directly
//   y[1024] = sum_c x[c]*(-1)^c             (closed form, done in prep)
//   E[y^2] = 0.5*(sum x^2 + sum x[c]*x[(2048-c)%2048])
// GEMM: Z[m,k] = sum_{c=1..1024} s[c]*cos(2 pi k c/2048)  = y[m,k]-mu[m]
//   M=16384, N=1024, K=1024, fp16 in / fp32 accum via mma.sync (HMMA).

#define ROWS 16384
#define CDIM 2048
#define KG   1024
#define NG   1024
#define BM   128
#define BN   128
#define BKC  64
#define STAGES 3
#define KITERS (KG / BKC)     // 16
#define EPS  1e-5f

__device__ __half g_S[(size_t)ROWS * KG];   // folded inputs fp16, [m][c-1] k-contig
__device__ __half g_T[(size_t)NG * KG];     // cos table fp16,     [k][c-1] k-contig
__device__ float  g_rs[ROWS];

__device__ __forceinline__ uint32_t smem_u32(const void* p) {
    uint32_t a;
    asm("{ .reg .u64 t; cvta.to.shared.u64 t, %1; cvt.u32.u64 %0, t; }" : "=r"(a) : "l"(p));
    return a;
}
__device__ __forceinline__ void cp16(uint32_t s, const void* g) {
    asm volatile("cp.async.cg.shared.global [%0], [%1], 16;" :: "r"(s), "l"(g) : "memory");
}
#define CP_COMMIT() asm volatile("cp.async.commit_group;" ::: "memory")

__device__ __forceinline__ void ldm_x4(uint32_t* r, uint32_t a) {
    asm volatile("ldmatrix.sync.aligned.m8n8.x4.shared.b16 {%0,%1,%2,%3}, [%4];"
                 : "=r"(r[0]), "=r"(r[1]), "=r"(r[2]), "=r"(r[3]) : "r"(a));
}
__device__ __forceinline__ void mma16816(float* c, const uint32_t* a, const uint32_t* b) {
    asm volatile("mma.sync.aligned.m16n8k16.row.col.f32.f16.f16.f32 "
                 "{%0,%1,%2,%3}, {%4,%5,%6,%7}, {%8,%9}, {%0,%1,%2,%3};"
                 : "+f"(c[0]), "+f"(c[1]), "+f"(c[2]), "+f"(c[3])
                 : "r"(a[0]), "r"(a[1]), "r"(a[2]), "r"(a[3]), "r"(b[0]), "r"(b[1]));
}

// ---------------------------------------------------------------- init table
// T[k][c-1] = cospi(k*c/1024); k*c <= 1023*1024 < 2^24: exact fp32 arg.
__global__ __launch_bounds__(256) void init_table_kernel() {
    int idx = blockIdx.x * blockDim.x + threadIdx.x;    // < NG*KG
    int k = idx >> 10;
    int ci = idx & 1023;
    g_T[idx] = __float2half(cospif((float)(k * (ci + 1)) * (1.0f / 1024.0f)));
}

// ---------------------------------------------------------------- prep
__global__ __launch_bounds__(256) void prep_kernel(const float* __restrict__ x,
                                                   const float* __restrict__ gamma,
                                                   const float* __restrict__ beta,
                                                   float* __restrict__ out) {
    __shared__ float sx[CDIM];
    __shared__ float w1[8], w2[8], w3[8];
    int row = blockIdx.x;
    int tid = threadIdx.x;
    const float* xr = x + (size_t)row * CDIM;

    float sumsq = 0.0f, alt = 0.0f;
    #pragma unroll
    for (int i = tid; i < CDIM; i += 256) {
        float v = xr[i];
        sx[i] = v;
        sumsq += v * v;
        alt += (i & 1) ? -v : v;
    }
    __syncthreads();

    float sumrev = 0.0f;
    #pragma unroll
    for (int i = tid; i < CDIM; i += 256) {
        sumrev += sx[i] * sx[(CDIM - i) & (CDIM - 1)];
    }

    __half* Sr = g_S + (size_t)row * KG;
    #pragma unroll
    for (int idx = tid; idx < KG; idx += 256) {
        int c = idx + 1;
        float v = (c == 1024) ? sx[1024] : (sx[c] + sx[CDIM - c]);
        Sr[idx] = __float2half(v);
    }

    #pragma unroll
    for (int o = 16; o > 0; o >>= 1) {
        sumsq  += __shfl_xor_sync(0xffffffffu, sumsq, o);
        sumrev += __shfl_xor_sync(0xffffffffu, sumrev, o);
        alt    += __shfl_xor_sync(0xffffffffu, alt, o);
    }
    if ((tid & 31) == 0) { w1[tid >> 5] = sumsq; w2[tid >> 5] = sumrev; w3[tid >> 5] = alt; }
    __syncthreads();
    if (tid == 0) {
        float a = 0.0f, b = 0.0f, al = 0.0f;
        #pragma unroll
        for (int i = 0; i < 8; i++) { a += w1[i]; b += w2[i]; al += w3[i]; }
        float mu = sx[0];
        float var = 0.5f * (a + b) - mu * mu;
        float rs = rsqrtf(var + EPS);
        g_rs[row] = rs;
        out[(size_t)row * CDIM + 1024] = (al - mu) * rs * gamma[1024] + beta[1024];
    }
}

// ---------------------------------------------------------------- GEMM + LN
// smem: 3 stages x (A 16KB + B 16KB). Row = 128B, SW128 xor swizzle:
//   chunk' = chunk ^ (row & 7)   (16B chunks, 8 per row)
#define STAGE_BYTES 32768
#define SMEM_SZ (STAGES * STAGE_BYTES)

__global__ __launch_bounds__(256, 2) void gemm_ln_kernel(const float* __restrict__ gamma,
                                                         const float* __restrict__ beta,
                                                         float* __restrict__ out) {
    extern __shared__ __align__(1024) uint8_t smem[];
    const uint32_t sbase = smem_u32(smem);
    const int tid = threadIdx.x;
    const int wid = tid >> 5;
    const int lane = tid & 31;
    const int m0 = blockIdx.y * BM;
    const int n0 = blockIdx.x * BN;

    // ---- cp.async producer mapping: thread -> (row, 4 chunks)
    const int ldrow = tid >> 1;
    const int ldc0 = (tid & 1) * 4;
    const __half* gA = g_S + (size_t)(m0 + ldrow) * KG + ldc0 * 8;
    const __half* gB = g_T + (size_t)(n0 + ldrow) * KG + ldc0 * 8;
    const uint32_t ldrowoff = (uint32_t)ldrow * 128u;
    const int ldrx = ldrow & 7;

    // ---- consumer mapping
    const int wm = wid & 1;            // 2 warps along m -> warp tile m64
    const int wn = wid >> 1;           // 4 warps along n -> warp tile n32
    uint32_t rowa_off[4]; int rxa;
    {
        int rbase = wm * 64 + (lane & 15);
        rxa = 0; // per-mf row differs only by multiples of 16 -> same (row&7)
        #pragma unroll
        for (int mf = 0; mf < 4; mf++) rowa_off[mf] = (uint32_t)(rbase + mf * 16) * 128u;
        rxa = rbase & 7;
    }
    const int csel_a = lane >> 4;       // 0/1: k-half
    uint32_t rowb_off[2]; int rxb;
    {
        int nb = wn * 32 + ((lane >> 4) << 3) + (lane & 7);
        #pragma unroll
        for (int g = 0; g < 2; g++) rowb_off[g] = (uint32_t)(nb + g * 16) * 128u;
        rxb = nb & 7;
    }
    const int csel_b = (lane >> 3) & 1;

    float acc[4][4][4];
    #pragma unroll
    for (int i = 0; i < 4; i++)
        #pragma unroll
        for (int j = 0; j < 4; j++)
            #pragma unroll
            for (int r = 0; r < 4; r++) acc[i][j][r] = 0.0f;

    auto load_stage = [&](int stage, int kc) {
        uint32_t sA = sbase + (uint32_t)stage * STAGE_BYTES;
        uint32_t sB = sA + 16384u;
        const __half* pa = gA + kc * BKC;
        const __half* pb = gB + kc * BKC;
        #pragma unroll
        for (int i = 0; i < 4; i++) {
            int c = ldc0 + i;
            uint32_t so = ldrowoff + (uint32_t)((c ^ ldrx) << 4);
            cp16(sA + so, pa + i * 8);
            cp16(sB + so, pb + i * 8);
        }
        CP_COMMIT();
    };

    load_stage(0, 0);
    load_stage(1, 1);

    for (int k = 0; k < KITERS; k++) {
        if (k < KITERS - 1) asm volatile("cp.async.wait_group 1;" ::: "memory");
        else                asm volatile("cp.async.wait_group 0;" ::: "memory");
        __syncthreads();

        uint32_t stA = sbase + (uint32_t)(k % STAGES) * STAGE_BYTES;
        uint32_t stB = stA + 16384u;

        #pragma unroll
        for (int ks = 0; ks < 4; ks++) {
            uint32_t a[4][4], b[2][4];
            int cha = (2 * ks + csel_a) ^ rxa;
            #pragma unroll
            for (int mf = 0; mf < 4; mf++)
                ldm_x4(a[mf], stA + rowa_off[mf] + (uint32_t)(cha << 4));
            int chb = (2 * ks + csel_b) ^ rxb;
            #pragma unroll
            for (int g = 0; g < 2; g++)
                ldm_x4(b[g], stB + rowb_off[g] + (uint32_t)(chb << 4));
            // b[g]: r0,r1 = (n 0-7 of group) {b0,b1}; r2,r3 = (n 8-15) {b0,b1}
            #pragma unroll
            for (int mf = 0; mf < 4; mf++) {
                mma16816(acc[mf][0], a[mf], &b[0][0]);
                mma16816(acc[mf][1], a[mf], &b[0][2]);
                mma16816(acc[mf][2], a[mf], &b[1][0]);
                mma16816(acc[mf][3], a[mf], &b[1][2]);
            }
        }

        __syncthreads();
        if (k + 2 < KITERS) load_stage((k + 2) % STAGES, k + 2);
    }

    // ---- epilogue: z = acc*rs; out[n] = z*gamma+beta; mirror to 2048-n
    #pragma unroll
    for (int mf = 0; mf < 4; mf++) {
        int r0 = m0 + wm * 64 + mf * 16 + (lane >> 2);
        int r1 = r0 + 8;
        float rs0 = g_rs[r0], rs1 = g_rs[r1];
        float* o0 = out + (size_t)r0 * CDIM;
        float* o1 = out + (size_t)r1 * CDIM;
        #pragma unroll
        for (int nf = 0; nf < 4; nf++) {
            int n = n0 + wn * 32 + nf * 8 + 2 * (lane & 3);
            float2 gg = *(const float2*)(gamma + n);
            float2 bb = *(const float2*)(beta + n);
            float z00 = acc[mf][nf][0] * rs0, z01 = acc[mf][nf][1] * rs0;
            float z10 = acc[mf][nf][2] * rs1, z11 = acc[mf][nf][3] * rs1;
            *(float2*)(o0 + n) = make_float2(z00 * gg.x + bb.x, z01 * gg.y + bb.y);
            *(float2*)(o1 + n) = make_float2(z10 * gg.x + bb.x, z11 * gg.y + bb.y);
            // mirrors: col n -> 2048-n (n>=1), col n+1 -> 2047-n
            float gm1 = gamma[2047 - n], bm1 = beta[2047 - n];
            o0[2047 - n] = z01 * gm1 + bm1;
            o1[2047 - n] = z11 * gm1 + bm1;
            if (n > 0) {
                float gm0 = gamma[2048 - n], bm0 = beta[2048 - n];
                o0[2048 - n] = z00 * gm0 + bm0;
                o1[2048 - n] = z10 * gm0 + bm0;
            }
        }
    }
}

// ---------------------------------------------------------------- launch
extern "C" void kernel_launch(void* const* d_in, const int* in_sizes, int n_in,
                              void* d_out, int out_size) {
    const float* x     = (const float*)d_in[0];
    const float* gamma = (const float*)d_in[1];
    const float* beta  = (const float*)d_in[2];
    float* out = (float*)d_out;

    init_table_kernel<<<(NG * KG) / 256, 256>>>();
    prep_kernel<<<ROWS, 256>>>(x, gamma, beta, out);

    cudaFuncSetAttribute(gemm_ln_kernel, cudaFuncAttributeMaxDynamicSharedMemorySize, SMEM_SZ);
    dim3 grid(NG / BN, ROWS / BM);   // (8, 128): n fastest -> A tiles stay L2-hot
    gemm_ln_kernel<<<grid, 256, SMEM_SZ>>>(gamma, beta, out);
}

// round 4
// speedup vs baseline: 6.4614x; 1.1934x over previous
#include <cuda_runtime.h>
#include <cuda_fp16.h>
#include <math.h>
#include <stdint.h>

// out = LayerNorm(Re(FFT(x, axis=-1))), x: (4,4096,2048) fp32.
// Radix-2 split of the folded cosine transform:
//   s[c] = x[c]+x[2048-c] (c=1..1023), s[1024]=x[1024]; c=0 dropped (== mean)
//   E[k] = sum_{d=1..512} s[2d]   cos(pi k d   /512 )   (E[1024-k] =  E[k])
//   O[k] = sum_{d=0..511} s[2d+1] cos(pi k(2d+1)/1024)  (O[1024-k] = -O[k])
//   y-mu:  [k]=E+O, [1024-k]=E-O (k=0..511); [512] = sum s[2d](-1)^d (prep)
//   outer mirror y[2048-k]=y[k]; var = 0.5*(sum x^2 + sum x[c]x[-c]) - mu^2
// GEMM: M=16384, K=512 x2 phases, N=512, fp16 in / fp32 accum, mma.sync.

#define ROWS 16384
#define CDIM 2048
#define BM   128
#define BNK  64          // k-columns per CTA
#define BKC  64          // K chunk
#define NT   16          // total chunks: 8 E-phase + 8 O-phase
#define STAGES 3
#define EPS  1e-5f

__device__ __half g_S[(size_t)ROWS * 1024];  // [m][0..511]=s_even(d=1..512), [512..1023]=s_odd
__device__ __half g_T[(size_t)512 * 1024];   // [k][0..511]=Be, [512..1023]=Bo
__device__ float  g_rs[ROWS];

__device__ __forceinline__ uint32_t smem_u32(const void* p) {
    uint32_t a;
    asm("{ .reg .u64 t; cvta.to.shared.u64 t, %1; cvt.u32.u64 %0, t; }" : "=r"(a) : "l"(p));
    return a;
}
__device__ __forceinline__ void cp16(uint32_t s, const void* g) {
    asm volatile("cp.async.cg.shared.global [%0], [%1], 16;" :: "r"(s), "l"(g) : "memory");
}
#define CP_COMMIT() asm volatile("cp.async.commit_group;" ::: "memory")

__device__ __forceinline__ void ldm_x4(uint32_t* r, uint32_t a) {
    asm volatile("ldmatrix.sync.aligned.m8n8.x4.shared.b16 {%0,%1,%2,%3}, [%4];"
                 : "=r"(r[0]), "=r"(r[1]), "=r"(r[2]), "=r"(r[3]) : "r"(a));
}
__device__ __forceinline__ void mma16816(float* c, const uint32_t* a, const uint32_t* b) {
    asm volatile("mma.sync.aligned.m16n8k16.row.col.f32.f16.f16.f32 "
                 "{%0,%1,%2,%3}, {%4,%5,%6,%7}, {%8,%9}, {%0,%1,%2,%3};"
                 : "+f"(c[0]), "+f"(c[1]), "+f"(c[2]), "+f"(c[3])
                 : "r"(a[0]), "r"(a[1]), "r"(a[2]), "r"(a[3]), "r"(b[0]), "r"(b[1]));
}

// ---------------------------------------------------------------- init table
// Be[k][j] = cospi(k*(j+1)/512)  (k*(j+1) <= 511*512 < 2^24: exact)
// Bo[k][d] = cospi(k*(2d+1)/1024)
__global__ __launch_bounds__(256) void init_table_kernel() {
    int idx = blockIdx.x * blockDim.x + threadIdx.x;   // < 512*1024
    int k = idx >> 10;
    int j = idx & 1023;
    float v;
    if (j < 512) v = cospif((float)(k * (j + 1)) * (1.0f / 512.0f));
    else         v = cospif((float)(k * (2 * (j - 512) + 1)) * (1.0f / 1024.0f));
    g_T[idx] = __float2half(v);
}

// ---------------------------------------------------------------- prep
__global__ __launch_bounds__(256) void prep_kernel(const float* __restrict__ x,
                                                   const float* __restrict__ gamma,
                                                   const float* __restrict__ beta,
                                                   float* __restrict__ out) {
    __shared__ float sx[CDIM];
    __shared__ float w1[8], w2[8], w3[8];
    int row = blockIdx.x;
    int tid = threadIdx.x;
    const float* xr = x + (size_t)row * CDIM;

    float sumsq = 0.0f;
    #pragma unroll
    for (int i = tid; i < CDIM; i += 256) {
        float v = xr[i];
        sx[i] = v;
        sumsq += v * v;
    }
    __syncthreads();

    float sumrev = 0.0f;
    #pragma unroll
    for (int i = tid; i < CDIM; i += 256) {
        sumrev += sx[i] * sx[(CDIM - i) & (CDIM - 1)];
    }

    // E[512] = sum_{d=1..512} s[2d]*(-1)^d
    float e512 = 0.0f;
    for (int d = tid + 1; d <= 512; d += 256) {
        float s2d = (d == 512) ? sx[1024] : (sx[2 * d] + sx[CDIM - 2 * d]);
        e512 += (d & 1) ? -s2d : s2d;
    }

    // folded + split storage
    __half* Sr = g_S + (size_t)row * 1024;
    #pragma unroll
    for (int j = tid; j < 1024; j += 256) {
        int c = (j < 512) ? (2 * j + 2) : (2 * (j - 512) + 1);
        float v = (c == 1024) ? sx[1024] : (sx[c] + sx[CDIM - c]);
        Sr[j] = __float2half(v);
    }

    #pragma unroll
    for (int o = 16; o > 0; o >>= 1) {
        sumsq  += __shfl_xor_sync(0xffffffffu, sumsq, o);
        sumrev += __shfl_xor_sync(0xffffffffu, sumrev, o);
        e512   += __shfl_xor_sync(0xffffffffu, e512, o);
    }
    if ((tid & 31) == 0) { w1[tid >> 5] = sumsq; w2[tid >> 5] = sumrev; w3[tid >> 5] = e512; }
    __syncthreads();
    if (tid == 0) {
        float a = 0.0f, b = 0.0f, e5 = 0.0f;
        #pragma unroll
        for (int i = 0; i < 8; i++) { a += w1[i]; b += w2[i]; e5 += w3[i]; }
        float mu = sx[0];
        float var = 0.5f * (a + b) - mu * mu;
        float rs = rsqrtf(var + EPS);
        g_rs[row] = rs;
        float z = e5 * rs;                      // y[512]-mu = E[512]
        float* orow = out + (size_t)row * CDIM;
        orow[512]  = z * gamma[512]  + beta[512];
        orow[1536] = z * gamma[1536] + beta[1536];
    }
}

// ---------------------------------------------------------------- GEMM + LN
// stage: A 128x64 fp16 (16KB) + B 64x64 fp16 (8KB) = 24KB; rows 128B, xor swizzle
#define STAGE_BYTES 24576
#define SMEM_SZ (STAGES * STAGE_BYTES)

__global__ __launch_bounds__(256, 2) void gemm_ln_kernel(const float* __restrict__ gamma,
                                                         const float* __restrict__ beta,
                                                         float* __restrict__ out) {
    extern __shared__ __align__(1024) uint8_t smem[];
    const uint32_t sbase = smem_u32(smem);
    const int tid = threadIdx.x;
    const int wid = tid >> 5;
    const int lane = tid & 31;
    const int m0 = blockIdx.y * BM;
    const int k0 = blockIdx.x * BNK;     // k-column tile base (0..511)

    // ---- producers
    const int arow = tid >> 1;                 // 128 rows, 4 chunks each
    const int ac0 = (tid & 1) * 4;
    const __half* gA = g_S + (size_t)(m0 + arow) * 1024 + ac0 * 8;
    const uint32_t aso = (uint32_t)arow * 128u;
    const int arx = arow & 7;
    const int brow = tid >> 2;                 // 64 rows, 2 chunks each
    const int bc0 = (tid & 3) * 2;
    const __half* gB = g_T + (size_t)(k0 + brow) * 1024 + bc0 * 8;
    const uint32_t bso = (uint32_t)brow * 128u;
    const int brx = brow & 7;

    // ---- consumers: 8 warps = 4 (m) x 2 (n); warp tile 32m x 32n
    const int wm = wid & 3;
    const int wn = wid >> 2;
    uint32_t rowa_off[2];
    {
        int rbase = wm * 32 + (lane & 15);
        rowa_off[0] = (uint32_t)rbase * 128u;
        rowa_off[1] = (uint32_t)(rbase + 16) * 128u;
    }
    const int rxa = lane & 7;
    const int csel_a = lane >> 4;
    uint32_t rowb_off[2];
    {
        int nb = wn * 32 + ((lane >> 4) << 3) + (lane & 7);
        rowb_off[0] = (uint32_t)nb * 128u;
        rowb_off[1] = (uint32_t)(nb + 16) * 128u;
    }
    const int rxb = lane & 7;
    const int csel_b = (lane >> 3) & 1;

    float accE[2][4][4], accO[2][4][4];
    #pragma unroll
    for (int i = 0; i < 2; i++)
        #pragma unroll
        for (int j = 0; j < 4; j++)
            #pragma unroll
            for (int r = 0; r < 4; r++) { accE[i][j][r] = 0.0f; accO[i][j][r] = 0.0f; }

    auto load_stage = [&](int stage, int t) {
        uint32_t sA = sbase + (uint32_t)stage * STAGE_BYTES;
        uint32_t sB = sA + 16384u;
        int koff = (t >> 3) * 512 + (t & 7) * BKC;    // phase*512 + kc*64
        const __half* pa = gA + koff;
        const __half* pb = gB + koff;
        #pragma unroll
        for (int i = 0; i < 4; i++) {
            int c = ac0 + i;
            cp16(sA + aso + (uint32_t)((c ^ arx) << 4), pa + i * 8);
        }
        #pragma unroll
        for (int i = 0; i < 2; i++) {
            int c = bc0 + i;
            cp16(sB + bso + (uint32_t)((c ^ brx) << 4), pb + i * 8);
        }
        CP_COMMIT();
    };

    load_stage(0, 0);
    load_stage(1, 1);

    int stage = 0;
    for (int t = 0; t < NT; t++) {
        if (t < NT - 1) asm volatile("cp.async.wait_group 1;" ::: "memory");
        else            asm volatile("cp.async.wait_group 0;" ::: "memory");
        __syncthreads();

        uint32_t stA = sbase + (uint32_t)stage * STAGE_BYTES;
        uint32_t stB = stA + 16384u;

        #pragma unroll
        for (int ks = 0; ks < 4; ks++) {
            uint32_t a[2][4], b[2][4];
            int cha = (2 * ks + csel_a) ^ rxa;
            ldm_x4(a[0], stA + rowa_off[0] + (uint32_t)(cha << 4));
            ldm_x4(a[1], stA + rowa_off[1] + (uint32_t)(cha << 4));
            int chb = (2 * ks + csel_b) ^ rxb;
            ldm_x4(b[0], stB + rowb_off[0] + (uint32_t)(chb << 4));
            ldm_x4(b[1], stB + rowb_off[1] + (uint32_t)(chb << 4));
            if (t < 8) {
                #pragma unroll
                for (int mf = 0; mf < 2; mf++) {
                    mma16816(accE[mf][0], a[mf], &b[0][0]);
                    mma16816(accE[mf][1], a[mf], &b[0][2]);
                    mma16816(accE[mf][2], a[mf], &b[1][0]);
                    mma16816(accE[mf][3], a[mf], &b[1][2]);
                }
            } else {
                #pragma unroll
                for (int mf = 0; mf < 2; mf++) {
                    mma16816(accO[mf][0], a[mf], &b[0][0]);
                    mma16816(accO[mf][1], a[mf], &b[0][2]);
                    mma16816(accO[mf][2], a[mf], &b[1][0]);
                    mma16816(accO[mf][3], a[mf], &b[1][2]);
                }
            }
        }

        __syncthreads();
        if (t + 2 < NT) load_stage((stage + 2) % STAGES, t + 2);
        if (++stage == STAGES) stage = 0;
    }

    // ---- epilogue: butterfly + LN + 4-region store
    float rsv[2][2];
    #pragma unroll
    for (int mf = 0; mf < 2; mf++) {
        int r0 = m0 + wm * 32 + mf * 16 + (lane >> 2);
        rsv[mf][0] = g_rs[r0];
        rsv[mf][1] = g_rs[r0 + 8];
    }
    const int kw = k0 + wn * 32 + 2 * (lane & 3);
    #pragma unroll
    for (int nf = 0; nf < 4; nf++) {
        int k = kw + nf * 8;                       // even, 0..510
        float g0 = __ldg(gamma + k),     be0 = __ldg(beta + k);
        float g1 = __ldg(gamma + k + 1), be1 = __ldg(beta + k + 1);
        float gm1 = __ldg(gamma + 2047 - k), bm1 = __ldg(beta + 2047 - k);
        float gm0 = 0.0f, bm0 = 0.0f;
        if (k > 0) { gm0 = __ldg(gamma + 2048 - k); bm0 = __ldg(beta + 2048 - k); }
        float gb0 = __ldg(gamma + 1024 - k), bb0 = __ldg(beta + 1024 - k);
        float gb1 = __ldg(gamma + 1023 - k), bb1 = __ldg(beta + 1023 - k);
        float gf0 = __ldg(gamma + 1024 + k), bf0 = __ldg(beta + 1024 + k);
        float gf1 = __ldg(gamma + 1025 + k), bf1 = __ldg(beta + 1025 + k);
        #pragma unroll
        for (int mf = 0; mf < 2; mf++) {
            int rbase = m0 + wm * 32 + mf * 16 + (lane >> 2);
            #pragma unroll
            for (int rp = 0; rp < 2; rp++) {
                float* o = out + (size_t)(rbase + rp * 8) * CDIM;
                float E0 = accE[mf][nf][rp * 2],     O0 = accO[mf][nf][rp * 2];
                float E1 = accE[mf][nf][rp * 2 + 1], O1 = accO[mf][nf][rp * 2 + 1];
                float r = rsv[mf][rp];
                float z0 = (E0 + O0) * r, z1 = (E1 + O1) * r;
                float w0 = (E0 - O0) * r, w1 = (E1 - O1) * r;
                *(float2*)(o + k) = make_float2(z0 * g0 + be0, z1 * g1 + be1);
                o[2047 - k] = z1 * gm1 + bm1;
                if (k > 0) o[2048 - k] = z0 * gm0 + bm0;
                o[1024 - k] = w0 * gb0 + bb0;
                o[1023 - k] = w1 * gb1 + bb1;
                if (k > 0) *(float2*)(o + 1024 + k) = make_float2(w0 * gf0 + bf0, w1 * gf1 + bf1);
                else       o[1025] = w1 * gf1 + bf1;
            }
        }
    }
}

// ---------------------------------------------------------------- launch
extern "C" void kernel_launch(void* const* d_in, const int* in_sizes, int n_in,
                              void* d_out, int out_size) {
    const float* x     = (const float*)d_in[0];
    const float* gamma = (const float*)d_in[1];
    const float* beta  = (const float*)d_in[2];
    float* out = (float*)d_out;

    init_table_kernel<<<(512 * 1024) / 256, 256>>>();
    prep_kernel<<<ROWS, 256>>>(x, gamma, beta, out);

    cudaFuncSetAttribute(gemm_ln_kernel, cudaFuncAttributeMaxDynamicSharedMemorySize, SMEM_SZ);
    dim3 grid(512 / BNK, ROWS / BM);   // (8, 128)
    gemm_ln_kernel<<<grid, 256, SMEM_SZ>>>(gamma, beta, out);
}

// round 5
// speedup vs baseline: 6.7708x; 1.0479x over previous
#include <cuda_runtime.h>
#include <cuda_fp16.h>
#include <math.h>
#include <stdint.h>

// out = LayerNorm(Re(FFT(x, axis=-1))), x: (4,4096,2048) fp32.
// Radix-2 split of the folded cosine transform:
//   s[c] = x[c]+x[2048-c] (c=1..1023), s[1024]=x[1024]; c=0 dropped (== mean)
//   E[k] = sum_{d=1..512} s[2d]   cos(pi k d   /512 )   (E[1024-k] =  E[k])
//   O[k] = sum_{d=0..511} s[2d+1] cos(pi k(2d+1)/1024)  (O[1024-k] = -O[k])
//   y-mu:  [k]=E+O, [1024-k]=E-O (k=0..511); [512] = sum s[2d](-1)^d (prep)
//   outer mirror y[2048-k]=y[k]; var = 0.5*(sum x^2 + sum x[c]x[-c]) - mu^2
// GEMM: M=16384, K=512 x2 phases, N=512, fp16 in / fp32 accum, mma.sync.

#define ROWS 16384
#define CDIM 2048
#define BM   128
#define BNK  64          // k-columns per CTA
#define BKC  64          // K chunk
#define NT   16          // total chunks: 8 E-phase + 8 O-phase
#define STAGES 4
#define TBLOCKS 2048     // table-init blocks appended to prep grid
#define EPS  1e-5f

__device__ __half g_S[(size_t)ROWS * 1024];  // [m][0..511]=s_even(d=1..512), [512..1023]=s_odd
__device__ __half g_T[(size_t)512 * 1024];   // [k][0..511]=Be, [512..1023]=Bo
__device__ float  g_rs[ROWS];

__device__ __forceinline__ uint32_t smem_u32(const void* p) {
    uint32_t a;
    asm("{ .reg .u64 t; cvta.to.shared.u64 t, %1; cvt.u32.u64 %0, t; }" : "=r"(a) : "l"(p));
    return a;
}
__device__ __forceinline__ void cp16(uint32_t s, const void* g) {
    asm volatile("cp.async.cg.shared.global [%0], [%1], 16;" :: "r"(s), "l"(g) : "memory");
}
#define CP_COMMIT() asm volatile("cp.async.commit_group;" ::: "memory")

__device__ __forceinline__ void ldm_x4(uint32_t* r, uint32_t a) {
    asm volatile("ldmatrix.sync.aligned.m8n8.x4.shared.b16 {%0,%1,%2,%3}, [%4];"
                 : "=r"(r[0]), "=r"(r[1]), "=r"(r[2]), "=r"(r[3]) : "r"(a));
}
__device__ __forceinline__ void mma16816(float* c, const uint32_t* a, const uint32_t* b) {
    asm volatile("mma.sync.aligned.m16n8k16.row.col.f32.f16.f16.f32 "
                 "{%0,%1,%2,%3}, {%4,%5,%6,%7}, {%8,%9}, {%0,%1,%2,%3};"
                 : "+f"(c[0]), "+f"(c[1]), "+f"(c[2]), "+f"(c[3])
                 : "r"(a[0]), "r"(a[1]), "r"(a[2]), "r"(a[3]), "r"(b[0]), "r"(b[1]));
}

// ---------------------------------------------------------------- prep + table
// blocks [0,ROWS): per-row fold/stats. blocks [ROWS, ROWS+TBLOCKS): cos tables.
// Be[k][j] = cospi(k*(j+1)/512); Bo[k][d] = cospi(k*(2d+1)/1024); args exact fp32.
__global__ __launch_bounds__(256) void prep_kernel(const float* __restrict__ x,
                                                   const float* __restrict__ gamma,
                                                   const float* __restrict__ beta,
                                                   float* __restrict__ out) {
    if (blockIdx.x >= ROWS) {
        int idx = (blockIdx.x - ROWS) * 256 + threadIdx.x;   // < 512*1024
        int k = idx >> 10;
        int j = idx & 1023;
        float v;
        if (j < 512) v = cospif((float)(k * (j + 1)) * (1.0f / 512.0f));
        else         v = cospif((float)(k * (2 * (j - 512) + 1)) * (1.0f / 1024.0f));
        g_T[idx] = __float2half(v);
        return;
    }

    __shared__ float sx[CDIM];
    __shared__ float w1[8], w2[8], w3[8];
    int row = blockIdx.x;
    int tid = threadIdx.x;
    const float* xr = x + (size_t)row * CDIM;

    float sumsq = 0.0f;
    #pragma unroll
    for (int i = tid; i < CDIM; i += 256) {
        float v = xr[i];
        sx[i] = v;
        sumsq += v * v;
    }
    __syncthreads();

    float sumrev = 0.0f;
    #pragma unroll
    for (int i = tid; i < CDIM; i += 256) {
        sumrev += sx[i] * sx[(CDIM - i) & (CDIM - 1)];
    }

    // E[512] = sum_{d=1..512} s[2d]*(-1)^d
    float e512 = 0.0f;
    for (int d = tid + 1; d <= 512; d += 256) {
        float s2d = (d == 512) ? sx[1024] : (sx[2 * d] + sx[CDIM - 2 * d]);
        e512 += (d & 1) ? -s2d : s2d;
    }

    __half* Sr = g_S + (size_t)row * 1024;
    #pragma unroll
    for (int j = tid; j < 1024; j += 256) {
        int c = (j < 512) ? (2 * j + 2) : (2 * (j - 512) + 1);
        float v = (c == 1024) ? sx[1024] : (sx[c] + sx[CDIM - c]);
        Sr[j] = __float2half(v);
    }

    #pragma unroll
    for (int o = 16; o > 0; o >>= 1) {
        sumsq  += __shfl_xor_sync(0xffffffffu, sumsq, o);
        sumrev += __shfl_xor_sync(0xffffffffu, sumrev, o);
        e512   += __shfl_xor_sync(0xffffffffu, e512, o);
    }
    if ((tid & 31) == 0) { w1[tid >> 5] = sumsq; w2[tid >> 5] = sumrev; w3[tid >> 5] = e512; }
    __syncthreads();
    if (tid == 0) {
        float a = 0.0f, b = 0.0f, e5 = 0.0f;
        #pragma unroll
        for (int i = 0; i < 8; i++) { a += w1[i]; b += w2[i]; e5 += w3[i]; }
        float mu = sx[0];
        float var = 0.5f * (a + b) - mu * mu;
        float rs = rsqrtf(var + EPS);
        g_rs[row] = rs;
        float z = e5 * rs;                      // y[512]-mu = E[512]
        float* orow = out + (size_t)row * CDIM;
        orow[512]  = z * gamma[512]  + beta[512];
        orow[1536] = z * gamma[1536] + beta[1536];
    }
}

// ---------------------------------------------------------------- GEMM + LN
// stage: A 128x64 fp16 (16KB) + B 64x64 fp16 (8KB) = 24KB; rows 128B, xor swizzle
#define STAGE_BYTES 24576
#define SMEM_SZ (STAGES * STAGE_BYTES)

__global__ __launch_bounds__(256, 2) void gemm_ln_kernel(const float* __restrict__ gamma,
                                                         const float* __restrict__ beta,
                                                         float* __restrict__ out) {
    extern __shared__ __align__(1024) uint8_t smem[];
    const uint32_t sbase = smem_u32(smem);
    const int tid = threadIdx.x;
    const int wid = tid >> 5;
    const int lane = tid & 31;
    const int m0 = blockIdx.y * BM;
    const int k0 = blockIdx.x * BNK;     // k-column tile base (0..511)

    // ---- producers
    const int arow = tid >> 1;                 // 128 rows, 4 chunks each
    const int ac0 = (tid & 1) * 4;
    const __half* gA = g_S + (size_t)(m0 + arow) * 1024 + ac0 * 8;
    const uint32_t aso = (uint32_t)arow * 128u;
    const int arx = arow & 7;
    const int brow = tid >> 2;                 // 64 rows, 2 chunks each
    const int bc0 = (tid & 3) * 2;
    const __half* gB = g_T + (size_t)(k0 + brow) * 1024 + bc0 * 8;
    const uint32_t bso = (uint32_t)brow * 128u;
    const int brx = brow & 7;

    // ---- consumers: 8 warps = 4 (m) x 2 (n); warp tile 32m x 32n
    const int wm = wid & 3;
    const int wn = wid >> 2;
    uint32_t rowa_off[2];
    {
        int rbase = wm * 32 + (lane & 15);
        rowa_off[0] = (uint32_t)rbase * 128u;
        rowa_off[1] = (uint32_t)(rbase + 16) * 128u;
    }
    const int rxa = lane & 7;
    const int csel_a = lane >> 4;
    uint32_t rowb_off[2];
    {
        int nb = wn * 32 + ((lane >> 4) << 3) + (lane & 7);
        rowb_off[0] = (uint32_t)nb * 128u;
        rowb_off[1] = (uint32_t)(nb + 16) * 128u;
    }
    const int rxb = lane & 7;
    const int csel_b = (lane >> 3) & 1;

    float accE[2][4][4], accO[2][4][4];
    #pragma unroll
    for (int i = 0; i < 2; i++)
        #pragma unroll
        for (int j = 0; j < 4; j++)
            #pragma unroll
            for (int r = 0; r < 4; r++) { accE[i][j][r] = 0.0f; accO[i][j][r] = 0.0f; }

    auto load_stage = [&](int stage, int t) {
        uint32_t sA = sbase + (uint32_t)stage * STAGE_BYTES;
        uint32_t sB = sA + 16384u;
        int koff = (t >> 3) * 512 + (t & 7) * BKC;    // phase*512 + kc*64
        const __half* pa = gA + koff;
        const __half* pb = gB + koff;
        #pragma unroll
        for (int i = 0; i < 4; i++) {
            int c = ac0 + i;
            cp16(sA + aso + (uint32_t)((c ^ arx) << 4), pa + i * 8);
        }
        #pragma unroll
        for (int i = 0; i < 2; i++) {
            int c = bc0 + i;
            cp16(sB + bso + (uint32_t)((c ^ brx) << 4), pb + i * 8);
        }
        CP_COMMIT();
    };

    // prologue: 3 chunks in flight
    load_stage(0, 0);
    load_stage(1, 1);
    load_stage(2, 2);

    for (int t = 0; t < NT; t++) {
        // guarantee chunk t's group has landed
        if (t < NT - 2)      asm volatile("cp.async.wait_group 2;" ::: "memory");
        else if (t == NT - 2) asm volatile("cp.async.wait_group 1;" ::: "memory");
        else                  asm volatile("cp.async.wait_group 0;" ::: "memory");
        __syncthreads();   // also fences: all warps done reading stage (t-1)%STAGES

        // issue chunk t+3 into buffer (t+3)%4 == (t-1)%4 (safe after the sync)
        if (t + 3 < NT) load_stage((t + 3) & (STAGES - 1), t + 3);

        uint32_t stA = sbase + (uint32_t)(t & (STAGES - 1)) * STAGE_BYTES;
        uint32_t stB = stA + 16384u;

        #pragma unroll
        for (int ks = 0; ks < 4; ks++) {
            uint32_t a[2][4], b[2][4];
            int cha = (2 * ks + csel_a) ^ rxa;
            ldm_x4(a[0], stA + rowa_off[0] + (uint32_t)(cha << 4));
            ldm_x4(a[1], stA + rowa_off[1] + (uint32_t)(cha << 4));
            int chb = (2 * ks + csel_b) ^ rxb;
            ldm_x4(b[0], stB + rowb_off[0] + (uint32_t)(chb << 4));
            ldm_x4(b[1], stB + rowb_off[1] + (uint32_t)(chb << 4));
            if (t < 8) {
                #pragma unroll
                for (int mf = 0; mf < 2; mf++) {
                    mma16816(accE[mf][0], a[mf], &b[0][0]);
                    mma16816(accE[mf][1], a[mf], &b[0][2]);
                    mma16816(accE[mf][2], a[mf], &b[1][0]);
                    mma16816(accE[mf][3], a[mf], &b[1][2]);
                }
            } else {
                #pragma unroll
                for (int mf = 0; mf < 2; mf++) {
                    mma16816(accO[mf][0], a[mf], &b[0][0]);
                    mma16816(accO[mf][1], a[mf], &b[0][2]);
                    mma16816(accO[mf][2], a[mf], &b[1][0]);
                    mma16816(accO[mf][3], a[mf], &b[1][2]);
                }
            }
        }
    }

    // ---- epilogue: butterfly + LN + 4-region store
    float rsv[2][2];
    #pragma unroll
    for (int mf = 0; mf < 2; mf++) {
        int r0 = m0 + wm * 32 + mf * 16 + (lane >> 2);
        rsv[mf][0] = g_rs[r0];
        rsv[mf][1] = g_rs[r0 + 8];
    }
    const int kw = k0 + wn * 32 + 2 * (lane & 3);
    #pragma unroll
    for (int nf = 0; nf < 4; nf++) {
        int k = kw + nf * 8;                       // even, 0..510
        float g0 = __ldg(gamma + k),     be0 = __ldg(beta + k);
        float g1 = __ldg(gamma + k + 1), be1 = __ldg(beta + k + 1);
        float gm1 = __ldg(gamma + 2047 - k), bm1 = __ldg(beta + 2047 - k);
        float gm0 = 0.0f, bm0 = 0.0f;
        if (k > 0) { gm0 = __ldg(gamma + 2048 - k); bm0 = __ldg(beta + 2048 - k); }
        float gb0 = __ldg(gamma + 1024 - k), bb0 = __ldg(beta + 1024 - k);
        float gb1 = __ldg(gamma + 1023 - k), bb1 = __ldg(beta + 1023 - k);
        float gf0 = __ldg(gamma + 1024 + k), bf0 = __ldg(beta + 1024 + k);
        float gf1 = __ldg(gamma + 1025 + k), bf1 = __ldg(beta + 1025 + k);
        #pragma unroll
        for (int mf = 0; mf < 2; mf++) {
            int rbase = m0 + wm * 32 + mf * 16 + (lane >> 2);
            #pragma unroll
            for (int rp = 0; rp < 2; rp++) {
                float* o = out + (size_t)(rbase + rp * 8) * CDIM;
                float E0 = accE[mf][nf][rp * 2],     O0 = accO[mf][nf][rp * 2];
                float E1 = accE[mf][nf][rp * 2 + 1], O1 = accO[mf][nf][rp * 2 + 1];
                float r = rsv[mf][rp];
                float z0 = (E0 + O0) * r, z1 = (E1 + O1) * r;
                float w0 = (E0 - O0) * r, w1 = (E1 - O1) * r;
                *(float2*)(o + k) = make_float2(z0 * g0 + be0, z1 * g1 + be1);
                o[2047 - k] = z1 * gm1 + bm1;
                if (k > 0) o[2048 - k] = z0 * gm0 + bm0;
                o[1024 - k] = w0 * gb0 + bb0;
                o[1023 - k] = w1 * gb1 + bb1;
                if (k > 0) *(float2*)(o + 1024 + k) = make_float2(w0 * gf0 + bf0, w1 * gf1 + bf1);
                else       o[1025] = w1 * gf1 + bf1;
            }
        }
    }
}

// ---------------------------------------------------------------- launch
extern "C" void kernel_launch(void* const* d_in, const int* in_sizes, int n_in,
                              void* d_out, int out_size) {
    const float* x     = (const float*)d_in[0];
    const float* gamma = (const float*)d_in[1];
    const float* beta  = (const float*)d_in[2];
    float* out = (float*)d_out;

    prep_kernel<<<ROWS + TBLOCKS, 256>>>(x, gamma, beta, out);

    cudaFuncSetAttribute(gemm_ln_kernel, cudaFuncAttributeMaxDynamicSharedMemorySize, SMEM_SZ);
    dim3 grid(512 / BNK, ROWS / BM);   // (8, 128)
    gemm_ln_kernel<<<grid, 256, SMEM_SZ>>>(gamma, beta, out);
}